// round 9
// baseline (speedup 1.0000x reference)
#include <cuda_runtime.h>
#include <cuda_bf16.h>
#include <math.h>
#include <stdint.h>

#define B_ 8
#define L_ 4096
#define D_ 768
#define Y_ 2048
#define NLB 64                 // l-blocks (L/64)
#define NTILES 16384           // 64 lblk * 32 yblk * 8 b

// ---------------- device scratch (no allocations allowed) ----------------
__device__ __nv_bfloat16 g_xh[(size_t)B_ * L_ * D_];
__device__ __nv_bfloat16 g_xl[(size_t)B_ * L_ * D_];
__device__ __nv_bfloat16 g_Uh[(size_t)Y_ * D_];
__device__ __nv_bfloat16 g_Ul[(size_t)Y_ * D_];
__device__ __nv_bfloat16 g_Fh[(size_t)Y_ * D_];
__device__ __nv_bfloat16 g_Fl[(size_t)Y_ * D_];
__device__ float g_pm[(size_t)B_ * Y_ * NLB];
__device__ float g_ps[(size_t)B_ * Y_ * NLB];
__device__ float g_pn[(size_t)B_ * Y_ * NLB];
__device__ float g_y[(size_t)B_ * Y_];
__device__ float g_loss;

// ---------------- helpers ----------------
__device__ __forceinline__ uint32_t smem_u32(const void* p) {
    uint32_t a;
    asm("{ .reg .u64 t; cvta.to.shared.u64 t, %1; cvt.u32.u64 %0, t; }" : "=r"(a) : "l"(p));
    return a;
}
#define SWZ128(x) ((x) ^ (((x) >> 3) & 0x70))

#define CP16(dst, src) \
    asm volatile("cp.async.cg.shared.global [%0], [%1], 16;" :: "r"(dst), "l"(src))
#define CPCOMMIT() asm volatile("cp.async.commit_group;" ::: "memory")
#define CPWAIT1() asm volatile("cp.async.wait_group 1;" ::: "memory")
#define CPWAIT0() asm volatile("cp.async.wait_group 0;" ::: "memory")

__device__ __forceinline__ void ldsm_x4(uint32_t* r, uint32_t addr) {
    asm volatile("ldmatrix.sync.aligned.m8n8.x4.shared.b16 {%0,%1,%2,%3}, [%4];"
        : "=r"(r[0]), "=r"(r[1]), "=r"(r[2]), "=r"(r[3]) : "r"(addr));
}
#define MMA_BF16(d, a, b0, b1)                                                \
    asm volatile("mma.sync.aligned.m16n8k16.row.col.f32.bf16.bf16.f32 "       \
        "{%0,%1,%2,%3}, {%4,%5,%6,%7}, {%8,%9}, {%0,%1,%2,%3};"               \
        : "+f"((d)[0]), "+f"((d)[1]), "+f"((d)[2]), "+f"((d)[3])              \
        : "r"((a)[0]), "r"((a)[1]), "r"((a)[2]), "r"((a)[3]),                 \
          "r"(b0), "r"(b1))

// ---------------- split fp32 -> bf16 hi/lo ----------------
__global__ void split_kernel(const float* __restrict__ in,
                             __nv_bfloat16* __restrict__ hi,
                             __nv_bfloat16* __restrict__ lo, int n4) {
    int i = blockIdx.x * blockDim.x + threadIdx.x;
    if (i >= n4) return;
    float4 v = ((const float4*)in)[i];
    __nv_bfloat16 h0 = __float2bfloat16(v.x), h1 = __float2bfloat16(v.y);
    __nv_bfloat16 h2 = __float2bfloat16(v.z), h3 = __float2bfloat16(v.w);
    __nv_bfloat16 l0 = __float2bfloat16(v.x - __bfloat162float(h0));
    __nv_bfloat16 l1 = __float2bfloat16(v.y - __bfloat162float(h1));
    __nv_bfloat16 l2 = __float2bfloat16(v.z - __bfloat162float(h2));
    __nv_bfloat16 l3 = __float2bfloat16(v.w - __bfloat162float(h3));
    ((__nv_bfloat162*)hi)[i * 2 + 0] = __nv_bfloat162(h0, h1);
    ((__nv_bfloat162*)hi)[i * 2 + 1] = __nv_bfloat162(h2, h3);
    ((__nv_bfloat162*)lo)[i * 2 + 0] = __nv_bfloat162(l0, l1);
    ((__nv_bfloat162*)lo)[i * 2 + 1] = __nv_bfloat162(l2, l3);
}

// ------- persistent dual GEMM, 2 CTAs/SM, 64y x 64l tiles, K-chunk 64 -------
#define T8K 8192
#define STAGE_B 49152              // 6 tiles * 8KB
#define PART_OFF (2 * STAGE_B)     // 98304
#define SMEM_TOT (PART_OFF + 3 * 64 * 4 * 4)   // +3KB = 101376

__device__ __forceinline__ void issue_stage(uint32_t sb, int ls,
                                            int tid, int stride) {
    const int tl = ls / 12, ks = ls - tl * 12;
    const int t = blockIdx.x + tl * stride;
    const int lblk = t & 63, yblk = (t >> 6) & 31, b = t >> 11;
    const __nv_bfloat16* srcs[6] = {
        g_Uh + (size_t)(yblk * 64) * D_, g_Ul + (size_t)(yblk * 64) * D_,
        g_Fh + (size_t)(yblk * 64) * D_, g_Fl + (size_t)(yblk * 64) * D_,
        g_xh + ((size_t)b * L_ + lblk * 64) * D_,
        g_xl + ((size_t)b * L_ + lblk * 64) * D_
    };
    const uint32_t bufb = (uint32_t)(ls & 1) * STAGE_B;
#pragma unroll
    for (int j = 0; j < 12; j++) {
        const int gi = j * 256 + tid;
        const int tt = gi >> 9;            // tile 0..5 (512 x 16B chunks each)
        const int ci = gi & 511;
        const int row = ci >> 3;           // 0..63
        const int c16 = ci & 7;
        const char* src = (const char*)(srcs[tt] + (size_t)row * D_ + ks * 64) + c16 * 16;
        const uint32_t dst = sb + bufb + tt * T8K + SWZ128(row * 128 + c16 * 16);
        CP16(dst, src);
    }
    CPCOMMIT();
}

__global__ void __launch_bounds__(256, 2)
gemm_kernel() {
    extern __shared__ char smem[];
    const uint32_t sb = smem_u32(smem);
    float* partm = (float*)(smem + PART_OFF);          // [64][4]
    float* parts = partm + 64 * 4;
    float* partn = parts + 64 * 4;

    const int tid = threadIdx.x, lane = tid & 31, wid = tid >> 5;
    const int stride = gridDim.x;
    const int myN = (NTILES - blockIdx.x + stride - 1) / stride;
    const int total = 12 * myN;

    const int my = (wid & 1) * 32;         // y half
    const int nl = (wid >> 1) * 16;        // l quarter (16 wide)
    const int wcol = wid >> 1;             // 0..3

    // unswizzled base byte offsets (swizzle applied per load)
    const uint32_t aByte = (uint32_t)((my + (lane & 15)) * 128 + ((lane >> 4) << 4));
    const uint32_t bByte = (uint32_t)((nl + (lane & 7) + ((lane >> 4) & 1) * 8) * 128
                                      + (((lane >> 3) & 1) << 4));

    float attacc[2][2][4], tacc[2][2][4];
#pragma unroll
    for (int mt = 0; mt < 2; mt++)
#pragma unroll
        for (int nt = 0; nt < 2; nt++)
#pragma unroll
            for (int r = 0; r < 4; r++) { attacc[mt][nt][r] = 0.f; tacc[mt][nt][r] = 0.f; }

    issue_stage(sb, 0, tid, stride);
    if (total > 1) issue_stage(sb, 1, tid, stride);

    for (int ls = 0; ls < total; ls++) {
        if (ls == total - 1) { CPWAIT0(); } else { CPWAIT1(); }
        __syncthreads();
        const uint32_t bufo = sb + (uint32_t)(ls & 1) * STAGE_B;

#pragma unroll
        for (int kk = 0; kk < 4; kk++) {
            uint32_t bh[4], bl[4];
            {
                const uint32_t sw = SWZ128(bByte + (uint32_t)(kk * 32));
                ldsm_x4(bh, bufo + 4 * T8K + sw);
                ldsm_x4(bl, bufo + 5 * T8K + sw);
            }
#pragma unroll
            for (int mt = 0; mt < 2; mt++) {
                const uint32_t sw = SWZ128(aByte + (uint32_t)(mt * 16 * 128 + kk * 32));
                uint32_t uh[4], ul[4], fh[4], fl[4];
                ldsm_x4(uh, bufo + 0 * T8K + sw);
                ldsm_x4(ul, bufo + 1 * T8K + sw);
                ldsm_x4(fh, bufo + 2 * T8K + sw);
                ldsm_x4(fl, bufo + 3 * T8K + sw);
                MMA_BF16(attacc[mt][0], uh, bh[0], bh[1]);
                MMA_BF16(attacc[mt][0], uh, bl[0], bl[1]);
                MMA_BF16(attacc[mt][0], ul, bh[0], bh[1]);
                MMA_BF16(attacc[mt][1], uh, bh[2], bh[3]);
                MMA_BF16(attacc[mt][1], uh, bl[2], bl[3]);
                MMA_BF16(attacc[mt][1], ul, bh[2], bh[3]);
                MMA_BF16(tacc[mt][0], fh, bh[0], bh[1]);
                MMA_BF16(tacc[mt][0], fh, bl[0], bl[1]);
                MMA_BF16(tacc[mt][0], fl, bh[0], bh[1]);
                MMA_BF16(tacc[mt][1], fh, bh[2], bh[3]);
                MMA_BF16(tacc[mt][1], fh, bl[2], bl[3]);
                MMA_BF16(tacc[mt][1], fl, bh[2], bh[3]);
            }
        }
        __syncthreads();
        if (ls + 2 < total) issue_stage(sb, ls + 2, tid, stride);

        if ((ls % 12) == 11) {
            // ---- register-level partial softmax for this 64x64 tile ----
            const int t = blockIdx.x + (ls / 12) * stride;
            const int lblk = t & 63, yblk = (t >> 6) & 31, b = t >> 11;
#pragma unroll
            for (int mt = 0; mt < 2; mt++) {
#pragma unroll
                for (int half = 0; half < 2; half++) {
                    float a[4], tv[4];
#pragma unroll
                    for (int nt = 0; nt < 2; nt++) {
                        a[nt * 2 + 0] = attacc[mt][nt][half * 2 + 0];
                        a[nt * 2 + 1] = attacc[mt][nt][half * 2 + 1];
                        tv[nt * 2 + 0] = tacc[mt][nt][half * 2 + 0];
                        tv[nt * 2 + 1] = tacc[mt][nt][half * 2 + 1];
                    }
                    float m = fmaxf(fmaxf(a[0], a[1]), fmaxf(a[2], a[3]));
                    m = fmaxf(m, __shfl_xor_sync(0xffffffffu, m, 1));
                    m = fmaxf(m, __shfl_xor_sync(0xffffffffu, m, 2));
                    float S = 0.f, N = 0.f;
#pragma unroll
                    for (int j = 0; j < 4; j++) {
                        const float e = __expf(a[j] - m);
                        S += e;
                        N += e * tv[j];
                    }
                    S += __shfl_xor_sync(0xffffffffu, S, 1);
                    S += __shfl_xor_sync(0xffffffffu, S, 2);
                    N += __shfl_xor_sync(0xffffffffu, N, 1);
                    N += __shfl_xor_sync(0xffffffffu, N, 2);
                    if ((lane & 3) == 0) {
                        const int r = my + mt * 16 + half * 8 + (lane >> 2);
                        partm[r * 4 + wcol] = m;
                        parts[r * 4 + wcol] = S;
                        partn[r * 4 + wcol] = N;
                    }
                }
            }
            __syncthreads();
            if (tid < 64) {
                const float m0 = partm[tid * 4 + 0], m1 = partm[tid * 4 + 1];
                const float m2 = partm[tid * 4 + 2], m3 = partm[tid * 4 + 3];
                const float gm = fmaxf(fmaxf(m0, m1), fmaxf(m2, m3));
                const float e0 = __expf(m0 - gm), e1 = __expf(m1 - gm);
                const float e2 = __expf(m2 - gm), e3 = __expf(m3 - gm);
                const float S = parts[tid * 4 + 0] * e0 + parts[tid * 4 + 1] * e1
                              + parts[tid * 4 + 2] * e2 + parts[tid * 4 + 3] * e3;
                const float N = partn[tid * 4 + 0] * e0 + partn[tid * 4 + 1] * e1
                              + partn[tid * 4 + 2] * e2 + partn[tid * 4 + 3] * e3;
                const size_t idx = ((size_t)b * Y_ + yblk * 64 + tid) * NLB + lblk;
                g_pm[idx] = gm; g_ps[idx] = S; g_pn[idx] = N;
            }
#pragma unroll
            for (int mt = 0; mt < 2; mt++)
#pragma unroll
                for (int nt = 0; nt < 2; nt++)
#pragma unroll
                    for (int r = 0; r < 4; r++) {
                        attacc[mt][nt][r] = 0.f; tacc[mt][nt][r] = 0.f;
                    }
        }
    }
}

// ---------------- reduce 64 partials per row -> logits ----------------
__global__ void __launch_bounds__(256)
reduce_kernel(const float* __restrict__ bias) {
    const int rr = blockIdx.x * 8 + (threadIdx.x >> 5);
    const int lane = threadIdx.x & 31;
    const size_t base = (size_t)rr * NLB;
    const float ma = g_pm[base + lane], mb = g_pm[base + 32 + lane];
    const float ml = fmaxf(ma, mb);
    float gm = ml;
#pragma unroll
    for (int s = 16; s > 0; s >>= 1) gm = fmaxf(gm, __shfl_xor_sync(0xffffffffu, gm, s));
    const float sa = __expf(ma - gm), sb2 = __expf(mb - gm);
    float S = g_ps[base + lane] * sa + g_ps[base + 32 + lane] * sb2;
    float N = g_pn[base + lane] * sa + g_pn[base + 32 + lane] * sb2;
#pragma unroll
    for (int s = 16; s > 0; s >>= 1) {
        S += __shfl_xor_sync(0xffffffffu, S, s);
        N += __shfl_xor_sync(0xffffffffu, N, s);
    }
    if (lane == 0) g_y[rr] = N / S + bias[rr & (Y_ - 1)];
}

// ---------------- cross-entropy loss (target arrives int32) --------------
__global__ void loss_kernel(const int* __restrict__ target) {
    __shared__ float sred[256];
    const int tid = threadIdx.x;
    float total = 0.f;
    for (int b = 0; b < B_; b++) {
        const float* row = g_y + (size_t)b * Y_;
        float m = -INFINITY;
        for (int i = tid; i < Y_; i += 256) m = fmaxf(m, row[i]);
        sred[tid] = m; __syncthreads();
        for (int s = 128; s > 0; s >>= 1) {
            if (tid < s) sred[tid] = fmaxf(sred[tid], sred[tid + s]);
            __syncthreads();
        }
        m = sred[0]; __syncthreads();
        float sum = 0.f;
        for (int i = tid; i < Y_; i += 256) sum += __expf(row[i] - m);
        sred[tid] = sum; __syncthreads();
        for (int s = 128; s > 0; s >>= 1) {
            if (tid < s) sred[tid] += sred[tid + s];
            __syncthreads();
        }
        if (tid == 0) total += m + logf(sred[0]) - row[target[b]];
        __syncthreads();
    }
    if (tid == 0) g_loss = total / (float)B_;
}

__global__ void writeout_kernel(float* __restrict__ out, int out_size) {
    const int idx = blockIdx.x * blockDim.x + threadIdx.x;
    const int ny = B_ * Y_;
    if (out_size >= ny + 1) {
        if (idx == 0) out[0] = g_loss;
        if (idx < ny) out[(out_size - ny) + idx] = g_y[idx];
    } else if (out_size == ny) {
        if (idx < ny) out[idx] = g_y[idx];
    } else {
        if (idx == 0 && out_size >= 1) out[0] = g_loss;
    }
}

extern "C" void kernel_launch(void* const* d_in, const int* in_sizes, int n_in,
                              void* d_out, int out_size) {
    const float* x    = (const float*)d_in[0];
    const float* U    = (const float*)d_in[1];
    const float* F    = (const float*)d_in[2];
    const float* bias = (const float*)d_in[3];
    const int*   tg   = (const int*)d_in[4];

    void *xh, *xl, *Uh, *Ul, *Fh, *Fl;
    cudaGetSymbolAddress(&xh, g_xh); cudaGetSymbolAddress(&xl, g_xl);
    cudaGetSymbolAddress(&Uh, g_Uh); cudaGetSymbolAddress(&Ul, g_Ul);
    cudaGetSymbolAddress(&Fh, g_Fh); cudaGetSymbolAddress(&Fl, g_Fl);

    const int nx4 = B_ * L_ * D_ / 4;
    const int nw4 = Y_ * D_ / 4;
    split_kernel<<<(nx4 + 255) / 256, 256>>>(x, (__nv_bfloat16*)xh, (__nv_bfloat16*)xl, nx4);
    split_kernel<<<(nw4 + 255) / 256, 256>>>(U, (__nv_bfloat16*)Uh, (__nv_bfloat16*)Ul, nw4);
    split_kernel<<<(nw4 + 255) / 256, 256>>>(F, (__nv_bfloat16*)Fh, (__nv_bfloat16*)Fl, nw4);

    int nsm = 148;
    cudaDeviceGetAttribute(&nsm, cudaDevAttrMultiProcessorCount, 0);
    cudaFuncSetAttribute(gemm_kernel, cudaFuncAttributeMaxDynamicSharedMemorySize, SMEM_TOT);
    gemm_kernel<<<2 * nsm, 256, SMEM_TOT>>>();

    reduce_kernel<<<B_ * Y_ / 8, 256>>>(bias);
    loss_kernel<<<1, 256>>>(tg);
    writeout_kernel<<<(B_ * Y_ + 255) / 256, 256>>>((float*)d_out, out_size);
}